// round 1
// baseline (speedup 1.0000x reference)
#include <cuda_runtime.h>
#include <math.h>

#define TT 4096        // total tokens (B*T)
#define DDIM 2048
#define FDIM 2048
#define NE 8
#define TWO_F 4096
#define CAP 9216       // padded routed-row capacity: 8192 + 8*128
#define TILE 128

// ---------------- scratch (static device globals; no allocations) ----------------
__device__ __align__(128) float g_xg[(long)CAP * DDIM];     // gathered gate-scaled tokens (72MB)
__device__ __align__(128) float g_h[(long)CAP * TWO_F];     // GEMM1 output (144MB)
__device__ __align__(128) float g_act[(long)CAP * FDIM];    // swiglu output (72MB)
__device__ int   g_rowmap[CAP];
__device__ int   g_count[NE];
__device__ int   g_cursor[NE];
__device__ int   g_off[NE + 1];
__device__ int   g_tope[TT * 2];
__device__ float g_topg[TT * 2];

// ---------------- small kernels ----------------
__global__ void zero_counts_kernel() {
    if (threadIdx.x < NE) g_count[threadIdx.x] = 0;
}

// one block per token: 8 router dots, top-2, counts
__global__ void router_kernel(const float* __restrict__ x, const float* __restrict__ rw) {
    int t = blockIdx.x;
    const float* xr = x + (long)t * DDIM;
    float acc[NE];
#pragma unroll
    for (int e = 0; e < NE; e++) acc[e] = 0.f;
    for (int d = threadIdx.x; d < DDIM; d += 256) {
        float xv = xr[d];
        const float4* rp = (const float4*)(rw + (long)d * NE);
        float4 r0 = rp[0], r1 = rp[1];
        acc[0] += xv * r0.x; acc[1] += xv * r0.y; acc[2] += xv * r0.z; acc[3] += xv * r0.w;
        acc[4] += xv * r1.x; acc[5] += xv * r1.y; acc[6] += xv * r1.z; acc[7] += xv * r1.w;
    }
    __shared__ float s[256][NE];
#pragma unroll
    for (int e = 0; e < NE; e++) s[threadIdx.x][e] = acc[e];
    __syncthreads();
    __shared__ float sc[NE];
    if (threadIdx.x < NE) {
        float v = 0.f;
        for (int i = 0; i < 256; i++) v += s[i][threadIdx.x];
        sc[threadIdx.x] = v;
    }
    __syncthreads();
    if (threadIdx.x == 0) {
        int e1 = 0; float v1 = sc[0];
        for (int e = 1; e < NE; e++) if (sc[e] > v1) { v1 = sc[e]; e1 = e; }
        int e2 = -1; float v2 = -1e30f;
        for (int e = 0; e < NE; e++) if (e != e1 && sc[e] > v2) { v2 = sc[e]; e2 = e; }
        float gg1 = 1.f / (1.f + expf(-v1));
        float gg2 = 1.f / (1.f + expf(-v2));
        g_tope[t * 2 + 0] = e1; g_topg[t * 2 + 0] = gg1;
        g_tope[t * 2 + 1] = e2; g_topg[t * 2 + 1] = gg2;
        atomicAdd(&g_count[e1], 1);
        atomicAdd(&g_count[e2], 1);
    }
}

__global__ void offsets_kernel() {
    int off = 0;
    for (int e = 0; e < NE; e++) {
        g_off[e] = off;
        g_cursor[e] = off;
        off += (g_count[e] + TILE - 1) & ~(TILE - 1);
    }
    g_off[NE] = off;
}

// zero the pad rows of each expert segment, mark rowmap -1
__global__ void pad_zero_kernel() {
    int e = blockIdx.x;
    int start = g_off[e] + g_count[e];
    int end = g_off[e + 1];
    for (int r = start; r < end; r++) {
        if (threadIdx.x == 0) g_rowmap[r] = -1;
        float4* dst = (float4*)(g_xg + (long)r * DDIM);
        for (int i = threadIdx.x; i < DDIM / 4; i += 256)
            dst[i] = make_float4(0.f, 0.f, 0.f, 0.f);
    }
}

// one block per (token, slot): append gate-scaled token to its expert segment
__global__ void gather_kernel(const float* __restrict__ x) {
    int b = blockIdx.x;
    int t = b >> 1;
    int e = g_tope[b];
    float g = g_topg[b];
    __shared__ int spos;
    if (threadIdx.x == 0) {
        spos = atomicAdd(&g_cursor[e], 1);
        g_rowmap[spos] = t;
    }
    __syncthreads();
    int pos = spos;
    const float4* xr = (const float4*)(x + (long)t * DDIM);
    float4* dst = (float4*)(g_xg + (long)pos * DDIM);
    for (int i = threadIdx.x; i < DDIM / 4; i += 256) {
        float4 v = xr[i];
        v.x *= g; v.y *= g; v.z *= g; v.w *= g;
        dst[i] = v;
    }
}

// act = y0 * sigmoid(y0) * y1 over g_h -> g_act
__global__ void swiglu_kernel(int rows) {
    long idx = (long)blockIdx.x * blockDim.x + threadIdx.x;
    long total = (long)rows * FDIM;
    if (idx >= total) return;
    long r = idx >> 11;            // / FDIM
    int f = (int)(idx & (FDIM - 1));
    float y0 = g_h[r * TWO_F + f];
    float y1 = g_h[r * TWO_F + FDIM + f];
    g_act[idx] = y0 * y1 / (1.f + __expf(-y0));
}

// ---------------- 128x128x8 fp32 GEMM, C = A @ B^T ----------------
// EPI 0: plain store to C (ldc stride). EPI 1: scatter atomicAdd into C (=out) via g_rowmap.
// EXPERT: B indexed by expert segment (g_off), early-out past g_off[NE].
template <int EPI, bool EXPERT>
__global__ __launch_bounds__(256)
void gemm_kernel(const float* __restrict__ A, int lda,
                 const float* __restrict__ B, int ldb, long bstride,
                 float* __restrict__ C, int ldc, int Kdim) {
    int r0 = blockIdx.y * TILE;
    int c0 = blockIdx.x * TILE;
    const float* Bp = B;
    if (EXPERT) {
        if (r0 >= g_off[NE]) return;
        int e = 0;
        while (g_off[e + 1] <= r0) e++;
        Bp += (long)e * bstride;
    }
    __shared__ __align__(16) float As[2][8][TILE];
    __shared__ __align__(16) float Bs[2][8][TILE];
    int tid = threadIdx.x;
    int lrow = tid >> 1, lk = (tid & 1) << 2;
    int tx = tid & 15, ty = tid >> 4;
    const float* Ap = A + (long)(r0 + lrow) * lda + lk;
    const float* Bq = Bp + (long)(c0 + lrow) * ldb + lk;

    float acc[8][8];
#pragma unroll
    for (int i = 0; i < 8; i++)
#pragma unroll
        for (int j = 0; j < 8; j++) acc[i][j] = 0.f;

    {
        float4 av = *(const float4*)Ap;
        float4 bv = *(const float4*)Bq;
        As[0][lk + 0][lrow] = av.x; As[0][lk + 1][lrow] = av.y;
        As[0][lk + 2][lrow] = av.z; As[0][lk + 3][lrow] = av.w;
        Bs[0][lk + 0][lrow] = bv.x; Bs[0][lk + 1][lrow] = bv.y;
        Bs[0][lk + 2][lrow] = bv.z; Bs[0][lk + 3][lrow] = bv.w;
    }
    __syncthreads();

    int nk = Kdim >> 3;
    for (int ks = 0; ks < nk; ks++) {
        int s = ks & 1;
        if (ks + 1 < nk) {
            float4 av = *(const float4*)(Ap + (ks + 1) * 8);
            float4 bv = *(const float4*)(Bq + (ks + 1) * 8);
            int s2 = s ^ 1;
            As[s2][lk + 0][lrow] = av.x; As[s2][lk + 1][lrow] = av.y;
            As[s2][lk + 2][lrow] = av.z; As[s2][lk + 3][lrow] = av.w;
            Bs[s2][lk + 0][lrow] = bv.x; Bs[s2][lk + 1][lrow] = bv.y;
            Bs[s2][lk + 2][lrow] = bv.z; Bs[s2][lk + 3][lrow] = bv.w;
        }
#pragma unroll
        for (int kk = 0; kk < 8; kk++) {
            float4 a0 = *(const float4*)&As[s][kk][ty * 4];
            float4 a1 = *(const float4*)&As[s][kk][64 + ty * 4];
            float4 b0 = *(const float4*)&Bs[s][kk][tx * 4];
            float4 b1 = *(const float4*)&Bs[s][kk][64 + tx * 4];
            float a[8] = {a0.x, a0.y, a0.z, a0.w, a1.x, a1.y, a1.z, a1.w};
            float b[8] = {b0.x, b0.y, b0.z, b0.w, b1.x, b1.y, b1.z, b1.w};
#pragma unroll
            for (int i = 0; i < 8; i++)
#pragma unroll
                for (int j = 0; j < 8; j++) acc[i][j] += a[i] * b[j];
        }
        __syncthreads();
    }

#pragma unroll
    for (int i = 0; i < 8; i++) {
        int mi = (i < 4) ? (ty * 4 + i) : (64 + ty * 4 + i - 4);
        int m = r0 + mi;
        if (EPI == 1) {
            int t = g_rowmap[m];
            if (t < 0) continue;
            float* orow = C + (long)t * ldc + c0;
#pragma unroll
            for (int j = 0; j < 8; j++) {
                int cj = (j < 4) ? (tx * 4 + j) : (64 + tx * 4 + j - 4);
                atomicAdd(&orow[cj], acc[i][j]);
            }
        } else {
            float* crow = C + (long)m * ldc + c0;
            *(float4*)&crow[tx * 4]      = make_float4(acc[i][0], acc[i][1], acc[i][2], acc[i][3]);
            *(float4*)&crow[64 + tx * 4] = make_float4(acc[i][4], acc[i][5], acc[i][6], acc[i][7]);
        }
    }
}

// ---------------- launch ----------------
extern "C" void kernel_launch(void* const* d_in, const int* in_sizes, int n_in,
                              void* d_out, int out_size) {
    const float* x    = (const float*)d_in[0];  // (B,T,D) = (TT, D)
    const float* rw   = (const float*)d_in[1];  // (D, E)
    const float* sw13 = (const float*)d_in[2];  // (2F, D)
    const float* sw2  = (const float*)d_in[3];  // (D, F)
    const float* rw13 = (const float*)d_in[4];  // (E, 2F, D)
    const float* rw2  = (const float*)d_in[5];  // (E, D, F)
    float* out = (float*)d_out;                 // (TT, D)

    float *xg, *h, *act;
    cudaGetSymbolAddress((void**)&xg, g_xg);
    cudaGetSymbolAddress((void**)&h, g_h);
    cudaGetSymbolAddress((void**)&act, g_act);

    // routing plumbing
    zero_counts_kernel<<<1, 32>>>();
    router_kernel<<<TT, 256>>>(x, rw);
    offsets_kernel<<<1, 1>>>();
    pad_zero_kernel<<<NE, 256>>>();
    gather_kernel<<<TT * 2, 256>>>(x);

    // shared expert: out = swiglu(x @ w13^T) @ w2^T   (plain store into out)
    gemm_kernel<0, false><<<dim3(TWO_F / TILE, TT / TILE), 256>>>(
        x, DDIM, sw13, DDIM, 0, h, TWO_F, DDIM);
    swiglu_kernel<<<((long)TT * FDIM + 255) / 256, 256>>>(TT);
    gemm_kernel<0, false><<<dim3(DDIM / TILE, TT / TILE), 256>>>(
        act, FDIM, sw2, FDIM, 0, out, DDIM, FDIM);

    // routed experts: h = xg @ w13_e^T ; act = swiglu(h) ; out += act @ w2_e^T (scatter)
    gemm_kernel<0, true><<<dim3(TWO_F / TILE, CAP / TILE), 256>>>(
        xg, DDIM, rw13, DDIM, (long)TWO_F * DDIM, h, TWO_F, DDIM);
    swiglu_kernel<<<((long)CAP * FDIM + 255) / 256, 256>>>(CAP);
    gemm_kernel<1, true><<<dim3(DDIM / TILE, CAP / TILE), 256>>>(
        act, FDIM, rw2, FDIM, (long)DDIM * FDIM, out, DDIM, FDIM);
}

// round 8
// speedup vs baseline: 3.8485x; 3.8485x over previous
#include <cuda_runtime.h>
#include <cuda_fp16.h>
#include <stdint.h>
#include <math.h>

typedef unsigned int u32;

#define TT 4096        // total tokens (B*T)
#define DDIM 2048
#define FDIM 2048
#define NE 8
#define TWO_F 4096
#define CAP 9216       // padded routed-row capacity: 8192 + 8*128
#define TILE 128
#define KT 32          // GEMM k-tile (halves)
#define STAGE_H (128 * 40)             // halves per array per stage (40-half padded rows)
#define STAGE_B (STAGE_H * 2)          // bytes per stage = 10240
#define SMEM_BYTES (3 * 2 * STAGE_B)   // 3 arrays x 2 stages = 61440

// ---------------- scratch (static device globals; no allocations) ----------------
__device__ __align__(128) __half g_xh[TT * DDIM];          // x hi
__device__ __align__(128) __half g_xl[TT * DDIM];          // x lo
__device__ __align__(128) __half g_xgh[CAP * DDIM];        // gathered gate-scaled tokens hi
__device__ __align__(128) __half g_xgl[CAP * DDIM];        // lo
__device__ __align__(128) float  g_h[(long)CAP * TWO_F];   // GEMM1 out (fp32); reused as routed-z (ld DDIM)
__device__ __align__(128) __half g_acth[CAP * FDIM];       // swiglu out hi
__device__ __align__(128) __half g_actl[CAP * FDIM];       // lo
__device__ __align__(128) __half g_sw13h[TWO_F * DDIM];
__device__ __align__(128) __half g_sw2h[DDIM * FDIM];
__device__ __align__(128) __half g_rw13h[NE * TWO_F * DDIM];
__device__ __align__(128) __half g_rw2h[NE * DDIM * FDIM];
__device__ int   g_count[NE];
__device__ int   g_cursor[NE];
__device__ int   g_off[NE + 1];
__device__ int   g_tope[TT * 2];
__device__ float g_topg[TT * 2];
__device__ int   g_slot[TT * 2];

// ---------------- inline PTX helpers ----------------
__device__ __forceinline__ void cp_async16(u32 dst, const void* src) {
    asm volatile("cp.async.cg.shared.global [%0], [%1], 16;\n" :: "r"(dst), "l"(src));
}
__device__ __forceinline__ void cp_commit() {
    asm volatile("cp.async.commit_group;\n" ::: "memory");
}
__device__ __forceinline__ void cp_wait0() {
    asm volatile("cp.async.wait_group 0;\n" ::: "memory");
}
__device__ __forceinline__ void ldsm4(u32* r, u32 addr) {
    asm volatile("ldmatrix.sync.aligned.m8n8.x4.shared.b16 {%0,%1,%2,%3}, [%4];\n"
                 : "=r"(r[0]), "=r"(r[1]), "=r"(r[2]), "=r"(r[3])
                 : "r"(addr));
}
__device__ __forceinline__ void mma16816(float* d, const u32* a, u32 b0, u32 b1) {
    asm volatile(
        "mma.sync.aligned.m16n8k16.row.col.f32.f16.f16.f32 "
        "{%0,%1,%2,%3},{%4,%5,%6,%7},{%8,%9},{%0,%1,%2,%3};\n"
        : "+f"(d[0]), "+f"(d[1]), "+f"(d[2]), "+f"(d[3])
        : "r"(a[0]), "r"(a[1]), "r"(a[2]), "r"(a[3]), "r"(b0), "r"(b1));
}

// ---------------- small kernels ----------------
__global__ void zero_counts_kernel() {
    if (threadIdx.x < NE) g_count[threadIdx.x] = 0;
}

// one block per token: 8 router dots (fp32), top-2, counts
__global__ void router_kernel(const float* __restrict__ x, const float* __restrict__ rw) {
    int t = blockIdx.x;
    const float* xr = x + (long)t * DDIM;
    float acc[NE];
#pragma unroll
    for (int e = 0; e < NE; e++) acc[e] = 0.f;
    for (int d = threadIdx.x; d < DDIM; d += 256) {
        float xv = xr[d];
        const float4* rp = (const float4*)(rw + (long)d * NE);
        float4 r0 = rp[0], r1 = rp[1];
        acc[0] += xv * r0.x; acc[1] += xv * r0.y; acc[2] += xv * r0.z; acc[3] += xv * r0.w;
        acc[4] += xv * r1.x; acc[5] += xv * r1.y; acc[6] += xv * r1.z; acc[7] += xv * r1.w;
    }
    __shared__ float s[256][NE];
#pragma unroll
    for (int e = 0; e < NE; e++) s[threadIdx.x][e] = acc[e];
    __syncthreads();
    __shared__ float sc[NE];
    if (threadIdx.x < NE) {
        float v = 0.f;
        for (int i = 0; i < 256; i++) v += s[i][threadIdx.x];
        sc[threadIdx.x] = v;
    }
    __syncthreads();
    if (threadIdx.x == 0) {
        int e1 = 0; float v1 = sc[0];
        for (int e = 1; e < NE; e++) if (sc[e] > v1) { v1 = sc[e]; e1 = e; }
        int e2 = -1; float v2 = -1e30f;
        for (int e = 0; e < NE; e++) if (e != e1 && sc[e] > v2) { v2 = sc[e]; e2 = e; }
        g_tope[t * 2 + 0] = e1; g_topg[t * 2 + 0] = 1.f / (1.f + expf(-v1));
        g_tope[t * 2 + 1] = e2; g_topg[t * 2 + 1] = 1.f / (1.f + expf(-v2));
        atomicAdd(&g_count[e1], 1);
        atomicAdd(&g_count[e2], 1);
    }
}

__global__ void offsets_kernel() {
    int off = 0;
    for (int e = 0; e < NE; e++) {
        g_off[e] = off;
        g_cursor[e] = off;
        off += (g_count[e] + TILE - 1) & ~(TILE - 1);
    }
    g_off[NE] = off;
}

// zero pad rows of each expert segment in xg hi/lo
__global__ void pad_zero_kernel() {
    int e = blockIdx.x;
    int start = g_off[e] + g_count[e];
    int end = g_off[e + 1];
    __half2 z = __floats2half2_rn(0.f, 0.f);
    for (int r = start; r < end; r++) {
        __half2* dh = (__half2*)(g_xgh + (long)r * DDIM);
        __half2* dl = (__half2*)(g_xgl + (long)r * DDIM);
        for (int i = threadIdx.x; i < DDIM / 2; i += 256) { dh[i] = z; dl[i] = z; }
    }
}

__device__ __forceinline__ void split2(float a, float b, __half2& h, __half2& l) {
    __half ha = __float2half_rn(a), hb = __float2half_rn(b);
    h = __halves2half2(ha, hb);
    l = __floats2half2_rn(a - __half2float(ha), b - __half2float(hb));
}

// one block per (token, slot): append gate-scaled token (split fp16) to its expert segment
__global__ void gather_kernel(const float* __restrict__ x) {
    int b = blockIdx.x;
    int t = b >> 1;
    float g = g_topg[b];
    __shared__ int spos;
    if (threadIdx.x == 0) {
        spos = atomicAdd(&g_cursor[g_tope[b]], 1);
        g_slot[b] = spos;
    }
    __syncthreads();
    int pos = spos;
    const float4* xr = (const float4*)(x + (long)t * DDIM);
    __half2* dh = (__half2*)(g_xgh + (long)pos * DDIM);
    __half2* dl = (__half2*)(g_xgl + (long)pos * DDIM);
    for (int i = threadIdx.x; i < DDIM / 4; i += 256) {
        float4 v = xr[i];
        __half2 h0, l0, h1, l1;
        split2(v.x * g, v.y * g, h0, l0);
        split2(v.z * g, v.w * g, h1, l1);
        dh[2 * i] = h0; dh[2 * i + 1] = h1;
        dl[2 * i] = l0; dl[2 * i + 1] = l1;
    }
}

// fp32 -> fp16 (weights)
__global__ void cvt_f16_kernel(const float4* __restrict__ in, __half2* __restrict__ out, int n4) {
    int i = blockIdx.x * blockDim.x + threadIdx.x;
    if (i >= n4) return;
    float4 v = in[i];
    out[2 * i]     = __floats2half2_rn(v.x, v.y);
    out[2 * i + 1] = __floats2half2_rn(v.z, v.w);
}

// fp32 -> fp16 hi + lo residual (x)
__global__ void split_f16_kernel(const float4* __restrict__ in, __half2* __restrict__ hi,
                                 __half2* __restrict__ lo, int n4) {
    int i = blockIdx.x * blockDim.x + threadIdx.x;
    if (i >= n4) return;
    float4 v = in[i];
    __half2 h0, l0, h1, l1;
    split2(v.x, v.y, h0, l0);
    split2(v.z, v.w, h1, l1);
    hi[2 * i] = h0; hi[2 * i + 1] = h1;
    lo[2 * i] = l0; lo[2 * i + 1] = l1;
}

// act = y0*sigmoid(y0)*y1 over g_h -> act hi/lo fp16
__global__ void swiglu_kernel(int rows) {
    long idx = (long)blockIdx.x * blockDim.x + threadIdx.x;
    long total = (long)rows * FDIM;
    if (idx >= total) return;
    long r = idx >> 11;
    int f = (int)(idx & (FDIM - 1));
    float y0 = g_h[r * TWO_F + f];
    float y1 = g_h[r * TWO_F + FDIM + f];
    float a = y0 * y1 / (1.f + __expf(-y0));
    __half h = __float2half_rn(a);
    g_acth[idx] = h;
    g_actl[idx] = __float2half_rn(a - __half2float(h));
}

// out[t] += zr[slot0] + zr[slot1]   (zr = g_h viewed with row stride DDIM)
__global__ void combine_kernel(float* __restrict__ out) {
    int t = blockIdx.x;
    int s0 = g_slot[2 * t], s1 = g_slot[2 * t + 1];
    const float4* z0 = (const float4*)(g_h + (long)s0 * DDIM);
    const float4* z1 = (const float4*)(g_h + (long)s1 * DDIM);
    float4* o = (float4*)(out + (long)t * DDIM);
    for (int i = threadIdx.x; i < DDIM / 4; i += 256) {
        float4 a = o[i], b = z0[i], c = z1[i];
        a.x += b.x + c.x; a.y += b.y + c.y; a.z += b.z + c.z; a.w += b.w + c.w;
        o[i] = a;
    }
}

// ---------------- fp16 tensor-core GEMM: C = (Ah+Al) @ B^T ----------------
template <bool EXPERT>
__global__ __launch_bounds__(256, 2)
void gemm_f16_kernel(const __half* __restrict__ Ah, const __half* __restrict__ Al,
                     const __half* __restrict__ B, long bstride,
                     float* __restrict__ C, int ldc, int Kdim) {
    int r0 = blockIdx.y * TILE;
    int c0 = blockIdx.x * TILE;
    const __half* Bp = B;
    if (EXPERT) {
        if (r0 >= g_off[NE]) return;
        int e = 0;
        while (g_off[e + 1] <= r0) e++;
        Bp += (long)e * bstride;
    }
    extern __shared__ __half smem[];
    u32 uAh = (u32)__cvta_generic_to_shared(smem);
    u32 uAl = uAh + 2 * STAGE_B;
    u32 uB  = uAh + 4 * STAGE_B;

    int tid = threadIdx.x, lane = tid & 31, wid = tid >> 5;
    int wm = wid & 3, wn = wid >> 2;

    // global->smem mapping: 512 16B-chunks per array; thread handles chunks tid, tid+256
    int rA = tid >> 2, va = tid & 3;
    int rB = rA + 64, vb = va;
    const char* gAh1 = (const char*)(Ah + (long)(r0 + rA) * Kdim + va * 8);
    const char* gAh2 = (const char*)(Ah + (long)(r0 + rB) * Kdim + vb * 8);
    const char* gAl1 = (const char*)(Al + (long)(r0 + rA) * Kdim + va * 8);
    const char* gAl2 = (const char*)(Al + (long)(r0 + rB) * Kdim + vb * 8);
    const char* gB1  = (const char*)(Bp + (long)(c0 + rA) * Kdim + va * 8);
    const char* gB2  = (const char*)(Bp + (long)(c0 + rB) * Kdim + vb * 8);
    u32 s1 = (u32)(rA * 80 + va * 16);
    u32 s2 = (u32)(rB * 80 + vb * 16);

    float acc[2][8][4];
#pragma unroll
    for (int i = 0; i < 2; i++)
#pragma unroll
        for (int j = 0; j < 8; j++)
#pragma unroll
            for (int k = 0; k < 4; k++) acc[i][j][k] = 0.f;

    // ldmatrix byte offsets within a stage (80-byte padded rows)
    u32 aoff = (u32)((wm * 32 + (lane & 15)) * 80 + (lane >> 4) * 16);
    u32 boff = (u32)((wn * 64 + ((lane >> 4) << 3) + (lane & 7)) * 80 + ((lane >> 3) & 1) * 16);

    int nk = Kdim >> 5;
    // prologue: stage 0
    cp_async16(uAh + s1, gAh1); cp_async16(uAh + s2, gAh2);
    cp_async16(uAl + s1, gAl1); cp_async16(uAl + s2, gAl2);
    cp_async16(uB  + s1, gB1);  cp_async16(uB  + s2, gB2);
    cp_commit();

    for (int kt = 0; kt < nk; kt++) {
        int st = kt & 1;
        cp_wait0();
        __syncthreads();
        if (kt + 1 < nk) {
            u32 so = (u32)(st ^ 1) * STAGE_B;
            long kb = (long)(kt + 1) * (KT * 2);
            cp_async16(uAh + so + s1, gAh1 + kb); cp_async16(uAh + so + s2, gAh2 + kb);
            cp_async16(uAl + so + s1, gAl1 + kb); cp_async16(uAl + so + s2, gAl2 + kb);
            cp_async16(uB  + so + s1, gB1 + kb);  cp_async16(uB  + so + s2, gB2 + kb);
            cp_commit();
        }
        u32 so = (u32)st * STAGE_B;
#pragma unroll
        for (int ks = 0; ks < 2; ks++) {
            u32 kb = (u32)ks * 32;  // 16 halves = 32 bytes
            u32 ah0[4], ah1[4], al0[4], al1[4];
            ldsm4(ah0, uAh + so + aoff + kb);
            ldsm4(ah1, uAh + so + aoff + 1280 + kb);
            ldsm4(al0, uAl + so + aoff + kb);
            ldsm4(al1, uAl + so + aoff + 1280 + kb);
#pragma unroll
            for (int np = 0; np < 4; np++) {
                u32 b[4];
                ldsm4(b, uB + so + boff + np * 1280 + kb);
                mma16816(acc[0][2 * np],     ah0, b[0], b[1]);
                mma16816(acc[0][2 * np + 1], ah0, b[2], b[3]);
                mma16816(acc[1][2 * np],     ah1, b[0], b[1]);
                mma16816(acc[1][2 * np + 1], ah1, b[2], b[3]);
                mma16816(acc[0][2 * np],     al0, b[0], b[1]);
                mma16816(acc[0][2 * np + 1], al0, b[2], b[3]);
                mma16816(acc[1][2 * np],     al1, b[0], b[1]);
                mma16816(acc[1][2 * np + 1], al1, b[2], b[3]);
            }
        }
    }

    // epilogue: plain stores
    int er = lane >> 2, ec = (lane & 3) * 2;
    int m_base = r0 + wm * 32, n_base = c0 + wn * 64;
#pragma unroll
    for (int mi = 0; mi < 2; mi++) {
#pragma unroll
        for (int nt = 0; nt < 8; nt++) {
            float* p = C + (long)(m_base + mi * 16 + er) * ldc + n_base + nt * 8 + ec;
            *(float2*)p = make_float2(acc[mi][nt][0], acc[mi][nt][1]);
            *(float2*)(p + (long)8 * ldc) = make_float2(acc[mi][nt][2], acc[mi][nt][3]);
        }
    }
}

// ---------------- launch ----------------
extern "C" void kernel_launch(void* const* d_in, const int* in_sizes, int n_in,
                              void* d_out, int out_size) {
    const float* x    = (const float*)d_in[0];  // (TT, D)
    const float* rw   = (const float*)d_in[1];  // (D, E)
    const float* sw13 = (const float*)d_in[2];  // (2F, D)
    const float* sw2  = (const float*)d_in[3];  // (D, F)
    const float* rw13 = (const float*)d_in[4];  // (E, 2F, D)
    const float* rw2  = (const float*)d_in[5];  // (E, D, F)
    float* out = (float*)d_out;                 // (TT, D)

    cudaFuncSetAttribute(gemm_f16_kernel<false>, cudaFuncAttributeMaxDynamicSharedMemorySize, SMEM_BYTES);
    cudaFuncSetAttribute(gemm_f16_kernel<true>,  cudaFuncAttributeMaxDynamicSharedMemorySize, SMEM_BYTES);

    __half *xh, *xl, *xgh, *xgl, *acth, *actl, *sw13h, *sw2h, *rw13h, *rw2h;
    float* h;
    cudaGetSymbolAddress((void**)&xh, g_xh);
    cudaGetSymbolAddress((void**)&xl, g_xl);
    cudaGetSymbolAddress((void**)&xgh, g_xgh);
    cudaGetSymbolAddress((void**)&xgl, g_xgl);
    cudaGetSymbolAddress((void**)&acth, g_acth);
    cudaGetSymbolAddress((void**)&actl, g_actl);
    cudaGetSymbolAddress((void**)&sw13h, g_sw13h);
    cudaGetSymbolAddress((void**)&sw2h, g_sw2h);
    cudaGetSymbolAddress((void**)&rw13h, g_rw13h);
    cudaGetSymbolAddress((void**)&rw2h, g_rw2h);
    cudaGetSymbolAddress((void**)&h, g_h);

    // routing + conversions
    zero_counts_kernel<<<1, 32>>>();
    router_kernel<<<TT, 256>>>(x, rw);
    offsets_kernel<<<1, 1>>>();
    pad_zero_kernel<<<NE, 256>>>();
    gather_kernel<<<TT * 2, 256>>>(x);

    {
        int n4 = TT * DDIM / 4;
        split_f16_kernel<<<(n4 + 255) / 256, 256>>>((const float4*)x, (__half2*)xh, (__half2*)xl, n4);
    }
    {
        int n4 = TWO_F * DDIM / 4;
        cvt_f16_kernel<<<(n4 + 255) / 256, 256>>>((const float4*)sw13, (__half2*)sw13h, n4);
    }
    {
        int n4 = DDIM * FDIM / 4;
        cvt_f16_kernel<<<(n4 + 255) / 256, 256>>>((const float4*)sw2, (__half2*)sw2h, n4);
    }
    {
        int n4 = NE * TWO_F * DDIM / 4;
        cvt_f16_kernel<<<(n4 + 255) / 256, 256>>>((const float4*)rw13, (__half2*)rw13h, n4);
    }
    {
        int n4 = NE * DDIM * FDIM / 4;
        cvt_f16_kernel<<<(n4 + 255) / 256, 256>>>((const float4*)rw2, (__half2*)rw2h, n4);
    }

    // shared expert: out = swiglu(x @ w13^T) @ w2^T
    gemm_f16_kernel<false><<<dim3(TWO_F / TILE, TT / TILE), 256, SMEM_BYTES>>>(
        xh, xl, sw13h, 0, h, TWO_F, DDIM);
    swiglu_kernel<<<(int)(((long)TT * FDIM + 255) / 256), 256>>>(TT);
    gemm_f16_kernel<false><<<dim3(DDIM / TILE, TT / TILE), 256, SMEM_BYTES>>>(
        acth, actl, sw2h, 0, out, DDIM, FDIM);

    // routed experts: h = xg @ w13_e^T ; act = swiglu(h) ; zr = act @ w2_e^T ; combine
    gemm_f16_kernel<true><<<dim3(TWO_F / TILE, CAP / TILE), 256, SMEM_BYTES>>>(
        xgh, xgl, rw13h, (long)TWO_F * DDIM, h, TWO_F, DDIM);
    swiglu_kernel<<<(int)(((long)CAP * FDIM + 255) / 256), 256>>>(CAP);
    gemm_f16_kernel<true><<<dim3(DDIM / TILE, CAP / TILE), 256, SMEM_BYTES>>>(
        acth, actl, rw2h, (long)DDIM * FDIM, h, DDIM, FDIM);
    combine_kernel<<<TT, 256>>>(out);
}

// round 9
// speedup vs baseline: 5.8868x; 1.5296x over previous
#include <cuda_runtime.h>
#include <cuda_fp16.h>
#include <stdint.h>
#include <math.h>

typedef unsigned int u32;

#define TT 4096        // total tokens (B*T)
#define DDIM 2048
#define FDIM 2048
#define NE 8
#define TWO_F 4096
#define CAP 9216       // padded routed-row capacity: 8192 + 8*128
#define TILE 128
#define KT 32          // GEMM k-tile (halves)
#define ARR_B 10240                    // bytes per array per stage (128 rows x 80B)
#define NSTAGE 3
#define SMEM_BYTES (2 * NSTAGE * ARR_B)  // A + B, 3 stages = 61440

// ---------------- scratch (static device globals; no allocations) ----------------
__device__ __align__(128) __half g_xh[TT * DDIM];          // x fp16
__device__ __align__(128) __half g_xgh[CAP * DDIM];        // gathered gate-scaled tokens fp16
__device__ __align__(128) float  g_h[(long)CAP * TWO_F];   // GEMM1 out (fp32); reused as routed-z (ld DDIM)
__device__ __align__(128) __half g_acth[CAP * FDIM];       // swiglu out fp16
__device__ __align__(128) __half g_sw13h[TWO_F * DDIM];
__device__ __align__(128) __half g_sw2h[DDIM * FDIM];
__device__ __align__(128) __half g_rw13h[NE * TWO_F * DDIM];
__device__ __align__(128) __half g_rw2h[NE * DDIM * FDIM];
__device__ int   g_count[NE];
__device__ int   g_cursor[NE];
__device__ int   g_off[NE + 1];
__device__ int   g_tope[TT * 2];
__device__ float g_topg[TT * 2];
__device__ int   g_slot[TT * 2];

// ---------------- inline PTX helpers ----------------
__device__ __forceinline__ void cp_async16(u32 dst, const void* src) {
    asm volatile("cp.async.cg.shared.global [%0], [%1], 16;\n" :: "r"(dst), "l"(src));
}
__device__ __forceinline__ void cp_commit() {
    asm volatile("cp.async.commit_group;\n" ::: "memory");
}
__device__ __forceinline__ void cp_wait1() {
    asm volatile("cp.async.wait_group 1;\n" ::: "memory");
}
__device__ __forceinline__ void ldsm4(u32* r, u32 addr) {
    asm volatile("ldmatrix.sync.aligned.m8n8.x4.shared.b16 {%0,%1,%2,%3}, [%4];\n"
                 : "=r"(r[0]), "=r"(r[1]), "=r"(r[2]), "=r"(r[3])
                 : "r"(addr));
}
__device__ __forceinline__ void mma16816(float* d, const u32* a, u32 b0, u32 b1) {
    asm volatile(
        "mma.sync.aligned.m16n8k16.row.col.f32.f16.f16.f32 "
        "{%0,%1,%2,%3},{%4,%5,%6,%7},{%8,%9},{%0,%1,%2,%3};\n"
        : "+f"(d[0]), "+f"(d[1]), "+f"(d[2]), "+f"(d[3])
        : "r"(a[0]), "r"(a[1]), "r"(a[2]), "r"(a[3]), "r"(b0), "r"(b1));
}

// ---------------- small kernels ----------------
__global__ void zero_counts_kernel() {
    if (threadIdx.x < NE) g_count[threadIdx.x] = 0;
}

// one block per token: 8 router dots (fp32), top-2, counts
__global__ void router_kernel(const float* __restrict__ x, const float* __restrict__ rw) {
    int t = blockIdx.x;
    const float* xr = x + (long)t * DDIM;
    float acc[NE];
#pragma unroll
    for (int e = 0; e < NE; e++) acc[e] = 0.f;
    for (int d = threadIdx.x; d < DDIM; d += 256) {
        float xv = xr[d];
        const float4* rp = (const float4*)(rw + (long)d * NE);
        float4 r0 = rp[0], r1 = rp[1];
        acc[0] += xv * r0.x; acc[1] += xv * r0.y; acc[2] += xv * r0.z; acc[3] += xv * r0.w;
        acc[4] += xv * r1.x; acc[5] += xv * r1.y; acc[6] += xv * r1.z; acc[7] += xv * r1.w;
    }
    __shared__ float s[256][NE];
#pragma unroll
    for (int e = 0; e < NE; e++) s[threadIdx.x][e] = acc[e];
    __syncthreads();
    __shared__ float sc[NE];
    if (threadIdx.x < NE) {
        float v = 0.f;
        for (int i = 0; i < 256; i++) v += s[i][threadIdx.x];
        sc[threadIdx.x] = v;
    }
    __syncthreads();
    if (threadIdx.x == 0) {
        int e1 = 0; float v1 = sc[0];
        for (int e = 1; e < NE; e++) if (sc[e] > v1) { v1 = sc[e]; e1 = e; }
        int e2 = -1; float v2 = -1e30f;
        for (int e = 0; e < NE; e++) if (e != e1 && sc[e] > v2) { v2 = sc[e]; e2 = e; }
        g_tope[t * 2 + 0] = e1; g_topg[t * 2 + 0] = 1.f / (1.f + expf(-v1));
        g_tope[t * 2 + 1] = e2; g_topg[t * 2 + 1] = 1.f / (1.f + expf(-v2));
        atomicAdd(&g_count[e1], 1);
        atomicAdd(&g_count[e2], 1);
    }
}

__global__ void offsets_kernel() {
    int off = 0;
    for (int e = 0; e < NE; e++) {
        g_off[e] = off;
        g_cursor[e] = off;
        off += (g_count[e] + TILE - 1) & ~(TILE - 1);
    }
    g_off[NE] = off;
}

// zero pad rows of each expert segment in xg
__global__ void pad_zero_kernel() {
    int e = blockIdx.x;
    int start = g_off[e] + g_count[e];
    int end = g_off[e + 1];
    __half2 z = __floats2half2_rn(0.f, 0.f);
    for (int r = start; r < end; r++) {
        __half2* dh = (__half2*)(g_xgh + (long)r * DDIM);
        for (int i = threadIdx.x; i < DDIM / 2; i += 256) dh[i] = z;
    }
}

// one block per (token, slot): append gate-scaled token (fp16) to its expert segment
__global__ void gather_kernel(const float* __restrict__ x) {
    int b = blockIdx.x;
    int t = b >> 1;
    float g = g_topg[b];
    __shared__ int spos;
    if (threadIdx.x == 0) {
        spos = atomicAdd(&g_cursor[g_tope[b]], 1);
        g_slot[b] = spos;
    }
    __syncthreads();
    int pos = spos;
    const float4* xr = (const float4*)(x + (long)t * DDIM);
    __half2* dh = (__half2*)(g_xgh + (long)pos * DDIM);
    for (int i = threadIdx.x; i < DDIM / 4; i += 256) {
        float4 v = xr[i];
        dh[2 * i]     = __floats2half2_rn(v.x * g, v.y * g);
        dh[2 * i + 1] = __floats2half2_rn(v.z * g, v.w * g);
    }
}

// fp32 -> fp16
__global__ void cvt_f16_kernel(const float4* __restrict__ in, __half2* __restrict__ out, int n4) {
    int i = blockIdx.x * blockDim.x + threadIdx.x;
    if (i >= n4) return;
    float4 v = in[i];
    out[2 * i]     = __floats2half2_rn(v.x, v.y);
    out[2 * i + 1] = __floats2half2_rn(v.z, v.w);
}

// act = y0*sigmoid(y0)*y1 over g_h -> act fp16
__global__ void swiglu_kernel(int rows) {
    long idx = (long)blockIdx.x * blockDim.x + threadIdx.x;
    long total = (long)rows * FDIM;
    if (idx >= total) return;
    long r = idx >> 11;
    int f = (int)(idx & (FDIM - 1));
    float y0 = g_h[r * TWO_F + f];
    float y1 = g_h[r * TWO_F + FDIM + f];
    float a = y0 * y1 / (1.f + __expf(-y0));
    g_acth[idx] = __float2half_rn(a);
}

// out[t] += zr[slot0] + zr[slot1]   (zr = g_h viewed with row stride DDIM)
__global__ void combine_kernel(float* __restrict__ out) {
    int t = blockIdx.x;
    int s0 = g_slot[2 * t], s1 = g_slot[2 * t + 1];
    const float4* z0 = (const float4*)(g_h + (long)s0 * DDIM);
    const float4* z1 = (const float4*)(g_h + (long)s1 * DDIM);
    float4* o = (float4*)(out + (long)t * DDIM);
    for (int i = threadIdx.x; i < DDIM / 4; i += 256) {
        float4 a = o[i], b = z0[i], c = z1[i];
        a.x += b.x + c.x; a.y += b.y + c.y; a.z += b.z + c.z; a.w += b.w + c.w;
        o[i] = a;
    }
}

// ---------------- fp16 tensor-core GEMM: C = A @ B^T (3-stage cp.async pipeline) ----------------
template <bool EXPERT>
__global__ __launch_bounds__(256, 2)
void gemm_f16_kernel(const __half* __restrict__ A,
                     const __half* __restrict__ B, long bstride,
                     float* __restrict__ C, int ldc, int Kdim) {
    int r0 = blockIdx.y * TILE;
    int c0 = blockIdx.x * TILE;
    const __half* Bp = B;
    if (EXPERT) {
        if (r0 >= g_off[NE]) return;
        int e = 0;
        while (g_off[e + 1] <= r0) e++;
        Bp += (long)e * bstride;
    }
    extern __shared__ __half smem[];
    u32 uA = (u32)__cvta_generic_to_shared(smem);
    u32 uB = uA + NSTAGE * ARR_B;

    int tid = threadIdx.x, lane = tid & 31, wid = tid >> 5;
    int wm = wid & 3, wn = wid >> 2;

    // global->smem mapping: 512 16B-chunks per array; thread handles chunks tid, tid+256
    int rA = tid >> 2, va = tid & 3;
    int rB = rA + 64;
    const char* gA1 = (const char*)(A + (long)(r0 + rA) * Kdim + va * 8);
    const char* gA2 = (const char*)(A + (long)(r0 + rB) * Kdim + va * 8);
    const char* gB1 = (const char*)(Bp + (long)(c0 + rA) * Kdim + va * 8);
    const char* gB2 = (const char*)(Bp + (long)(c0 + rB) * Kdim + va * 8);
    u32 s1 = (u32)(rA * 80 + va * 16);
    u32 s2 = (u32)(rB * 80 + va * 16);

    float acc[2][8][4];
#pragma unroll
    for (int i = 0; i < 2; i++)
#pragma unroll
        for (int j = 0; j < 8; j++)
#pragma unroll
            for (int k = 0; k < 4; k++) acc[i][j][k] = 0.f;

    // ldmatrix byte offsets within a stage (80-byte padded rows)
    u32 aoff = (u32)((wm * 32 + (lane & 15)) * 80 + (lane >> 4) * 16);
    u32 boff = (u32)((wn * 64 + ((lane >> 4) << 3) + (lane & 7)) * 80 + ((lane >> 3) & 1) * 16);

    int nk = Kdim >> 5;   // always >= 2 here (K = 2048)
    // prologue: stages 0 and 1
    cp_async16(uA + s1, gA1); cp_async16(uA + s2, gA2);
    cp_async16(uB + s1, gB1); cp_async16(uB + s2, gB2);
    cp_commit();
    cp_async16(uA + ARR_B + s1, gA1 + 64); cp_async16(uA + ARR_B + s2, gA2 + 64);
    cp_async16(uB + ARR_B + s1, gB1 + 64); cp_async16(uB + ARR_B + s2, gB2 + 64);
    cp_commit();

    int st = 0;
    for (int kt = 0; kt < nk; kt++) {
        cp_wait1();          // oldest in-flight stage (kt) is resident
        __syncthreads();
        if (kt + 2 < nk) {
            int sn = st + 2; if (sn >= NSTAGE) sn -= NSTAGE;
            u32 so = (u32)sn * ARR_B;
            long kb = (long)(kt + 2) * (KT * 2);
            cp_async16(uA + so + s1, gA1 + kb); cp_async16(uA + so + s2, gA2 + kb);
            cp_async16(uB + so + s1, gB1 + kb); cp_async16(uB + so + s2, gB2 + kb);
            cp_commit();
        } else {
            cp_commit();     // keep group count advancing so wait_group 1 drains correctly
        }
        u32 so = (u32)st * ARR_B;
#pragma unroll
        for (int ks = 0; ks < 2; ks++) {
            u32 kb = (u32)ks * 32;  // 16 halves = 32 bytes
            u32 a0[4], a1[4];
            ldsm4(a0, uA + so + aoff + kb);
            ldsm4(a1, uA + so + aoff + 1280 + kb);
#pragma unroll
            for (int np = 0; np < 4; np++) {
                u32 b[4];
                ldsm4(b, uB + so + boff + np * 1280 + kb);
                mma16816(acc[0][2 * np],     a0, b[0], b[1]);
                mma16816(acc[0][2 * np + 1], a0, b[2], b[3]);
                mma16816(acc[1][2 * np],     a1, b[0], b[1]);
                mma16816(acc[1][2 * np + 1], a1, b[2], b[3]);
            }
        }
        if (++st == NSTAGE) st = 0;
    }

    // epilogue: plain stores
    int er = lane >> 2, ec = (lane & 3) * 2;
    int m_base = r0 + wm * 32, n_base = c0 + wn * 64;
#pragma unroll
    for (int mi = 0; mi < 2; mi++) {
#pragma unroll
        for (int nt = 0; nt < 8; nt++) {
            float* p = C + (long)(m_base + mi * 16 + er) * ldc + n_base + nt * 8 + ec;
            *(float2*)p = make_float2(acc[mi][nt][0], acc[mi][nt][1]);
            *(float2*)(p + (long)8 * ldc) = make_float2(acc[mi][nt][2], acc[mi][nt][3]);
        }
    }
}

// ---------------- launch ----------------
extern "C" void kernel_launch(void* const* d_in, const int* in_sizes, int n_in,
                              void* d_out, int out_size) {
    const float* x    = (const float*)d_in[0];  // (TT, D)
    const float* rw   = (const float*)d_in[1];  // (D, E)
    const float* sw13 = (const float*)d_in[2];  // (2F, D)
    const float* sw2  = (const float*)d_in[3];  // (D, F)
    const float* rw13 = (const float*)d_in[4];  // (E, 2F, D)
    const float* rw2  = (const float*)d_in[5];  // (E, D, F)
    float* out = (float*)d_out;                 // (TT, D)

    cudaFuncSetAttribute(gemm_f16_kernel<false>, cudaFuncAttributeMaxDynamicSharedMemorySize, SMEM_BYTES);
    cudaFuncSetAttribute(gemm_f16_kernel<true>,  cudaFuncAttributeMaxDynamicSharedMemorySize, SMEM_BYTES);

    __half *xh, *xgh, *acth, *sw13h, *sw2h, *rw13h, *rw2h;
    float* h;
    cudaGetSymbolAddress((void**)&xh, g_xh);
    cudaGetSymbolAddress((void**)&xgh, g_xgh);
    cudaGetSymbolAddress((void**)&acth, g_acth);
    cudaGetSymbolAddress((void**)&sw13h, g_sw13h);
    cudaGetSymbolAddress((void**)&sw2h, g_sw2h);
    cudaGetSymbolAddress((void**)&rw13h, g_rw13h);
    cudaGetSymbolAddress((void**)&rw2h, g_rw2h);
    cudaGetSymbolAddress((void**)&h, g_h);

    // routing + conversions
    zero_counts_kernel<<<1, 32>>>();
    router_kernel<<<TT, 256>>>(x, rw);
    offsets_kernel<<<1, 1>>>();
    pad_zero_kernel<<<NE, 256>>>();
    gather_kernel<<<TT * 2, 256>>>(x);

    {
        int n4 = TT * DDIM / 4;
        cvt_f16_kernel<<<(n4 + 255) / 256, 256>>>((const float4*)x, (__half2*)xh, n4);
    }
    {
        int n4 = TWO_F * DDIM / 4;
        cvt_f16_kernel<<<(n4 + 255) / 256, 256>>>((const float4*)sw13, (__half2*)sw13h, n4);
    }
    {
        int n4 = DDIM * FDIM / 4;
        cvt_f16_kernel<<<(n4 + 255) / 256, 256>>>((const float4*)sw2, (__half2*)sw2h, n4);
    }
    {
        int n4 = NE * TWO_F * DDIM / 4;
        cvt_f16_kernel<<<(n4 + 255) / 256, 256>>>((const float4*)rw13, (__half2*)rw13h, n4);
    }
    {
        int n4 = NE * DDIM * FDIM / 4;
        cvt_f16_kernel<<<(n4 + 255) / 256, 256>>>((const float4*)rw2, (__half2*)rw2h, n4);
    }

    // shared expert: out = swiglu(x @ w13^T) @ w2^T
    gemm_f16_kernel<false><<<dim3(TWO_F / TILE, TT / TILE), 256, SMEM_BYTES>>>(
        xh, sw13h, 0, h, TWO_F, DDIM);
    swiglu_kernel<<<(int)(((long)TT * FDIM + 255) / 256), 256>>>(TT);
    gemm_f16_kernel<false><<<dim3(DDIM / TILE, TT / TILE), 256, SMEM_BYTES>>>(
        acth, sw2h, 0, out, DDIM, FDIM);

    // routed experts: h = xg @ w13_e^T ; act = swiglu(h) ; zr = act @ w2_e^T ; combine
    gemm_f16_kernel<true><<<dim3(TWO_F / TILE, CAP / TILE), 256, SMEM_BYTES>>>(
        xgh, rw13h, (long)TWO_F * DDIM, h, TWO_F, DDIM);
    swiglu_kernel<<<(int)(((long)CAP * FDIM + 255) / 256), 256>>>(CAP);
    gemm_f16_kernel<true><<<dim3(DDIM / TILE, CAP / TILE), 256, SMEM_BYTES>>>(
        acth, rw2h, (long)DDIM * FDIM, h, DDIM, FDIM);
    combine_kernel<<<TT, 256>>>(out);
}

// round 12
// speedup vs baseline: 6.8198x; 1.1585x over previous
#include <cuda_runtime.h>
#include <cuda_fp16.h>
#include <stdint.h>
#include <math.h>

typedef unsigned int u32;

#define TT 4096        // total tokens (B*T)
#define DDIM 2048
#define FDIM 2048
#define NE 8
#define TWO_F 4096
#define CAP 9216       // padded routed-row capacity: 8192 + 8*128
#define GT 128         // GEMM tile (M and N)
#define KT 64          // GEMM k-tile (halves) = 128 bytes/row
#define ROWB 144       // padded smem row stride in bytes (128 + 16)
#define STG_B (128 * ROWB)               // 18432 bytes per array per stage
#define NS 3
#define SMEM_BYTES (2 * NS * STG_B)      // A + B, 3 stages = 110592

// ---------------- scratch (static device globals; no allocations) ----------------
__device__ __align__(128) __half g_xh[TT * DDIM];          // x fp16
__device__ __align__(128) __half g_xgh[CAP * DDIM];        // gathered gate-scaled tokens fp16
__device__ __align__(128) float  g_h[(long)CAP * TWO_F];   // routed-z scratch (ld DDIM)
__device__ __align__(128) __half g_acth[CAP * FDIM];       // swiglu out fp16
__device__ __align__(128) __half g_sw13h[TWO_F * DDIM];    // interleaved rows
__device__ __align__(128) __half g_sw2h[DDIM * FDIM];
__device__ __align__(128) __half g_rw13h[NE * TWO_F * DDIM];  // interleaved rows per expert
__device__ __align__(128) __half g_rw2h[NE * DDIM * FDIM];
__device__ int   g_count[NE];
__device__ int   g_cursor[NE];
__device__ int   g_off[NE + 1];
__device__ int   g_tope[TT * 2];
__device__ float g_topg[TT * 2];
__device__ int   g_slot[TT * 2];

// ---------------- inline PTX helpers ----------------
__device__ __forceinline__ void cp_async16(u32 dst, const void* src) {
    asm volatile("cp.async.cg.shared.global [%0], [%1], 16;\n" :: "r"(dst), "l"(src));
}
__device__ __forceinline__ void cp_commit() {
    asm volatile("cp.async.commit_group;\n" ::: "memory");
}
__device__ __forceinline__ void cp_wait1() {
    asm volatile("cp.async.wait_group 1;\n" ::: "memory");
}
__device__ __forceinline__ void ldsm4(u32* r, u32 addr) {
    asm volatile("ldmatrix.sync.aligned.m8n8.x4.shared.b16 {%0,%1,%2,%3}, [%4];\n"
                 : "=r"(r[0]), "=r"(r[1]), "=r"(r[2]), "=r"(r[3])
                 : "r"(addr));
}
__device__ __forceinline__ void mma16816(float* d, const u32* a, u32 b0, u32 b1) {
    asm volatile(
        "mma.sync.aligned.m16n8k16.row.col.f32.f16.f16.f32 "
        "{%0,%1,%2,%3},{%4,%5,%6,%7},{%8,%9},{%0,%1,%2,%3};\n"
        : "+f"(d[0]), "+f"(d[1]), "+f"(d[2]), "+f"(d[3])
        : "r"(a[0]), "r"(a[1]), "r"(a[2]), "r"(a[3]), "r"(b0), "r"(b1));
}

// ---------------- small kernels ----------------
__global__ void zero_counts_kernel() {
    if (threadIdx.x < NE) g_count[threadIdx.x] = 0;
}

// one block per token: 8 router dots (fp32), top-2, counts
__global__ void router_kernel(const float* __restrict__ x, const float* __restrict__ rw) {
    int t = blockIdx.x;
    const float* xr = x + (long)t * DDIM;
    float acc[NE];
#pragma unroll
    for (int e = 0; e < NE; e++) acc[e] = 0.f;
    for (int d = threadIdx.x; d < DDIM; d += 256) {
        float xv = xr[d];
        const float4* rp = (const float4*)(rw + (long)d * NE);
        float4 r0 = rp[0], r1 = rp[1];
        acc[0] += xv * r0.x; acc[1] += xv * r0.y; acc[2] += xv * r0.z; acc[3] += xv * r0.w;
        acc[4] += xv * r1.x; acc[5] += xv * r1.y; acc[6] += xv * r1.z; acc[7] += xv * r1.w;
    }
    __shared__ float s[256][NE];
#pragma unroll
    for (int e = 0; e < NE; e++) s[threadIdx.x][e] = acc[e];
    __syncthreads();
    __shared__ float sc[NE];
    if (threadIdx.x < NE) {
        float v = 0.f;
        for (int i = 0; i < 256; i++) v += s[i][threadIdx.x];
        sc[threadIdx.x] = v;
    }
    __syncthreads();
    if (threadIdx.x == 0) {
        int e1 = 0; float v1 = sc[0];
        for (int e = 1; e < NE; e++) if (sc[e] > v1) { v1 = sc[e]; e1 = e; }
        int e2 = -1; float v2 = -1e30f;
        for (int e = 0; e < NE; e++) if (e != e1 && sc[e] > v2) { v2 = sc[e]; e2 = e; }
        g_tope[t * 2 + 0] = e1; g_topg[t * 2 + 0] = 1.f / (1.f + expf(-v1));
        g_tope[t * 2 + 1] = e2; g_topg[t * 2 + 1] = 1.f / (1.f + expf(-v2));
        atomicAdd(&g_count[e1], 1);
        atomicAdd(&g_count[e2], 1);
    }
}

__global__ void offsets_kernel() {
    int off = 0;
    for (int e = 0; e < NE; e++) {
        g_off[e] = off;
        g_cursor[e] = off;
        off += (g_count[e] + GT - 1) & ~(GT - 1);
    }
    g_off[NE] = off;
}

// zero pad rows of each expert segment in xg
__global__ void pad_zero_kernel() {
    int e = blockIdx.x;
    int start = g_off[e] + g_count[e];
    int end = g_off[e + 1];
    __half2 z = __floats2half2_rn(0.f, 0.f);
    for (int r = start; r < end; r++) {
        __half2* dh = (__half2*)(g_xgh + (long)r * DDIM);
        for (int i = threadIdx.x; i < DDIM / 2; i += 256) dh[i] = z;
    }
}

// one block per (token, slot): append gate-scaled token (fp16) to its expert segment
__global__ void gather_kernel(const float* __restrict__ x) {
    int b = blockIdx.x;
    int t = b >> 1;
    float g = g_topg[b];
    __shared__ int spos;
    if (threadIdx.x == 0) {
        spos = atomicAdd(&g_cursor[g_tope[b]], 1);
        g_slot[b] = spos;
    }
    __syncthreads();
    int pos = spos;
    const float4* xr = (const float4*)(x + (long)t * DDIM);
    __half2* dh = (__half2*)(g_xgh + (long)pos * DDIM);
    for (int i = threadIdx.x; i < DDIM / 4; i += 256) {
        float4 v = xr[i];
        dh[2 * i]     = __floats2half2_rn(v.x * g, v.y * g);
        dh[2 * i + 1] = __floats2half2_rn(v.z * g, v.w * g);
    }
}

// fp32 -> fp16 (plain)
__global__ void cvt_f16_kernel(const float4* __restrict__ in, __half2* __restrict__ out, int n4) {
    int i = blockIdx.x * blockDim.x + threadIdx.x;
    if (i >= n4) return;
    float4 v = in[i];
    out[2 * i]     = __floats2half2_rn(v.x, v.y);
    out[2 * i + 1] = __floats2half2_rn(v.z, v.w);
}

// fp32 -> fp16 with w13 row interleave: out row 2f <- in row f (w1), out row 2f+1 <- in row F+f (w3)
__global__ void cvt_i13_kernel(const float4* __restrict__ in, __half2* __restrict__ out, int n4) {
    int i = blockIdx.x * blockDim.x + threadIdx.x;
    if (i >= n4) return;
    float4 v = in[i];
    long elem = (long)i * 4;
    int row = (int)(elem >> 11);          // / DDIM
    int d   = (int)(elem & (DDIM - 1));
    int e = row >> 12;                    // / TWO_F
    int r = row & (TWO_F - 1);
    int rp = (r < FDIM) ? (2 * r) : (2 * (r - FDIM) + 1);
    long o = (((long)e * TWO_F + rp) << 11) + d;
    __half2* dst = out + (o >> 1);
    dst[0] = __floats2half2_rn(v.x, v.y);
    dst[1] = __floats2half2_rn(v.z, v.w);
}

// out[t] += zr[slot0] + zr[slot1]   (zr = g_h viewed with row stride DDIM)
__global__ void combine_kernel(float* __restrict__ out) {
    int t = blockIdx.x;
    int s0 = g_slot[2 * t], s1 = g_slot[2 * t + 1];
    const float4* z0 = (const float4*)(g_h + (long)s0 * DDIM);
    const float4* z1 = (const float4*)(g_h + (long)s1 * DDIM);
    float4* o = (float4*)(out + (long)t * DDIM);
    for (int i = threadIdx.x; i < DDIM / 4; i += 256) {
        float4 a = o[i], b = z0[i], c = z1[i];
        a.x += b.x + c.x; a.y += b.y + c.y; a.z += b.z + c.z; a.w += b.w + c.w;
        o[i] = a;
    }
}

// ---------------- fp16 tensor-core GEMM: C = A @ B^T (3-stage cp.async, KT=64) ----------------
// EPI 0: plain fp32 store to C (ldc stride).
// EPI 1: swiglu over adjacent col pairs (interleaved w13) -> fp16 store to C at col n/2.
template <int EPI, bool EXPERT>
__global__ __launch_bounds__(256, 2)
void gemm_f16_kernel(const __half* __restrict__ A,
                     const __half* __restrict__ B, long bstride,
                     void* __restrict__ Cv, int ldc, int Kdim) {
    int r0 = blockIdx.y * GT;
    int c0 = blockIdx.x * GT;
    const __half* Bp = B;
    if (EXPERT) {
        if (r0 >= g_off[NE]) return;
        int e = 0;
        while (g_off[e + 1] <= r0) e++;
        Bp += (long)e * bstride;
    }
    extern __shared__ __half smem[];
    u32 uA = (u32)__cvta_generic_to_shared(smem);
    u32 uB = uA + NS * STG_B;

    int tid = threadIdx.x, lane = tid & 31, wid = tid >> 5;
    int wm = wid & 3, wn = wid >> 2;

    // global->smem mapping: 1024 16B-chunks per array per stage; 4 chunks per thread
    const char* aP[4];
    const char* bP[4];
    u32 sOff[4];
#pragma unroll
    for (int i = 0; i < 4; i++) {
        int c = tid + 256 * i;
        int row = c >> 3, k16 = c & 7;
        aP[i] = (const char*)(A + (long)(r0 + row) * Kdim) + k16 * 16;
        bP[i] = (const char*)(Bp + (long)(c0 + row) * Kdim) + k16 * 16;
        sOff[i] = (u32)(row * ROWB + k16 * 16);
    }

    float acc[2][8][4];
#pragma unroll
    for (int i = 0; i < 2; i++)
#pragma unroll
        for (int j = 0; j < 8; j++)
#pragma unroll
            for (int k = 0; k < 4; k++) acc[i][j][k] = 0.f;

    // ldmatrix byte offsets within a stage (144-byte padded rows)
    u32 aoff = (u32)((wm * 32 + (lane & 15)) * ROWB + (lane >> 4) * 16);
    u32 boff = (u32)((wn * 64 + ((lane >> 4) << 3) + (lane & 7)) * ROWB + ((lane >> 3) & 1) * 16);

    int nk = Kdim >> 6;   // KT=64 stages; K=2048 -> 32
    // prologue: stages 0 and 1
#pragma unroll
    for (int s = 0; s < 2; s++) {
#pragma unroll
        for (int i = 0; i < 4; i++) {
            cp_async16(uA + (u32)s * STG_B + sOff[i], aP[i] + s * 128);
            cp_async16(uB + (u32)s * STG_B + sOff[i], bP[i] + s * 128);
        }
        cp_commit();
    }

    int st = 0;
    for (int kt = 0; kt < nk; kt++) {
        cp_wait1();          // stage kt resident
        __syncthreads();
        if (kt + 2 < nk) {
            int sn = st + 2; if (sn >= NS) sn -= NS;
            u32 ao = uA + (u32)sn * STG_B;
            u32 bo = uB + (u32)sn * STG_B;
            long kb = (long)(kt + 2) * 128;
#pragma unroll
            for (int i = 0; i < 4; i++) {
                cp_async16(ao + sOff[i], aP[i] + kb);
                cp_async16(bo + sOff[i], bP[i] + kb);
            }
        }
        cp_commit();
        u32 soA = uA + (u32)st * STG_B;
        u32 soB = uB + (u32)st * STG_B;
#pragma unroll
        for (int ks = 0; ks < 4; ks++) {
            u32 kb = (u32)ks * 32;  // 16 halves = 32 bytes
            u32 a0[4], a1[4];
            ldsm4(a0, soA + aoff + kb);
            ldsm4(a1, soA + aoff + 16 * ROWB + kb);   // rows +16 (was wrongly +32 in R11)
#pragma unroll
            for (int np = 0; np < 4; np++) {
                u32 b[4];
                ldsm4(b, soB + boff + (u32)np * 16 * ROWB + kb);
                mma16816(acc[0][2 * np],     a0, b[0], b[1]);
                mma16816(acc[0][2 * np + 1], a0, b[2], b[3]);
                mma16816(acc[1][2 * np],     a1, b[0], b[1]);
                mma16816(acc[1][2 * np + 1], a1, b[2], b[3]);
            }
        }
        if (++st == NS) st = 0;
    }

    // epilogue
    int er = lane >> 2, ec = (lane & 3) * 2;
    int m_base = r0 + wm * 32, n_base = c0 + wn * 64;
    if (EPI == 1) {
        __half* H = (__half*)Cv;
        int f0 = (c0 >> 1) + wn * 32 + (lane & 3);
#pragma unroll
        for (int mi = 0; mi < 2; mi++) {
            int rw0 = m_base + mi * 16 + er;
#pragma unroll
            for (int nt = 0; nt < 8; nt++) {
                int f = f0 + nt * 4;
                float y0 = acc[mi][nt][0], y1 = acc[mi][nt][1];
                H[(long)rw0 * ldc + f] = __float2half_rn(y0 * y1 / (1.f + __expf(-y0)));
                y0 = acc[mi][nt][2]; y1 = acc[mi][nt][3];
                H[(long)(rw0 + 8) * ldc + f] = __float2half_rn(y0 * y1 / (1.f + __expf(-y0)));
            }
        }
    } else {
        float* C = (float*)Cv;
#pragma unroll
        for (int mi = 0; mi < 2; mi++) {
#pragma unroll
            for (int nt = 0; nt < 8; nt++) {
                float* p = C + (long)(m_base + mi * 16 + er) * ldc + n_base + nt * 8 + ec;
                *(float2*)p = make_float2(acc[mi][nt][0], acc[mi][nt][1]);
                *(float2*)(p + (long)8 * ldc) = make_float2(acc[mi][nt][2], acc[mi][nt][3]);
            }
        }
    }
}

// ---------------- launch ----------------
extern "C" void kernel_launch(void* const* d_in, const int* in_sizes, int n_in,
                              void* d_out, int out_size) {
    const float* x    = (const float*)d_in[0];  // (TT, D)
    const float* rw   = (const float*)d_in[1];  // (D, E)
    const float* sw13 = (const float*)d_in[2];  // (2F, D)
    const float* sw2  = (const float*)d_in[3];  // (D, F)
    const float* rw13 = (const float*)d_in[4];  // (E, 2F, D)
    const float* rw2  = (const float*)d_in[5];  // (E, D, F)
    float* out = (float*)d_out;                 // (TT, D)

    cudaFuncSetAttribute(gemm_f16_kernel<0, false>, cudaFuncAttributeMaxDynamicSharedMemorySize, SMEM_BYTES);
    cudaFuncSetAttribute(gemm_f16_kernel<0, true>,  cudaFuncAttributeMaxDynamicSharedMemorySize, SMEM_BYTES);
    cudaFuncSetAttribute(gemm_f16_kernel<1, false>, cudaFuncAttributeMaxDynamicSharedMemorySize, SMEM_BYTES);
    cudaFuncSetAttribute(gemm_f16_kernel<1, true>,  cudaFuncAttributeMaxDynamicSharedMemorySize, SMEM_BYTES);

    __half *xh, *xgh, *acth, *sw13h, *sw2h, *rw13h, *rw2h;
    float* h;
    cudaGetSymbolAddress((void**)&xh, g_xh);
    cudaGetSymbolAddress((void**)&xgh, g_xgh);
    cudaGetSymbolAddress((void**)&acth, g_acth);
    cudaGetSymbolAddress((void**)&sw13h, g_sw13h);
    cudaGetSymbolAddress((void**)&sw2h, g_sw2h);
    cudaGetSymbolAddress((void**)&rw13h, g_rw13h);
    cudaGetSymbolAddress((void**)&rw2h, g_rw2h);
    cudaGetSymbolAddress((void**)&h, g_h);

    // routing + conversions
    zero_counts_kernel<<<1, 32>>>();
    router_kernel<<<TT, 256>>>(x, rw);
    offsets_kernel<<<1, 1>>>();
    pad_zero_kernel<<<NE, 256>>>();
    gather_kernel<<<TT * 2, 256>>>(x);

    {
        int n4 = TT * DDIM / 4;
        cvt_f16_kernel<<<(n4 + 255) / 256, 256>>>((const float4*)x, (__half2*)xh, n4);
    }
    {
        int n4 = TWO_F * DDIM / 4;
        cvt_i13_kernel<<<(n4 + 255) / 256, 256>>>((const float4*)sw13, (__half2*)sw13h, n4);
    }
    {
        int n4 = DDIM * FDIM / 4;
        cvt_f16_kernel<<<(n4 + 255) / 256, 256>>>((const float4*)sw2, (__half2*)sw2h, n4);
    }
    {
        int n4 = NE * TWO_F * DDIM / 4;
        cvt_i13_kernel<<<(n4 + 255) / 256, 256>>>((const float4*)rw13, (__half2*)rw13h, n4);
    }
    {
        int n4 = NE * DDIM * FDIM / 4;
        cvt_f16_kernel<<<(n4 + 255) / 256, 256>>>((const float4*)rw2, (__half2*)rw2h, n4);
    }

    // shared expert: acth = swiglu(x @ w13'^T) [fused epi]; out = acth @ w2^T
    gemm_f16_kernel<1, false><<<dim3(TWO_F / GT, TT / GT), 256, SMEM_BYTES>>>(
        xh, sw13h, 0, acth, FDIM, DDIM);
    gemm_f16_kernel<0, false><<<dim3(DDIM / GT, TT / GT), 256, SMEM_BYTES>>>(
        acth, sw2h, 0, out, DDIM, FDIM);

    // routed experts: acth = swiglu(xg @ w13'_e^T) [fused epi]; zr = acth @ w2_e^T ; combine
    gemm_f16_kernel<1, true><<<dim3(TWO_F / GT, CAP / GT), 256, SMEM_BYTES>>>(
        xgh, rw13h, (long)TWO_F * DDIM, acth, FDIM, DDIM);
    gemm_f16_kernel<0, true><<<dim3(DDIM / GT, CAP / GT), 256, SMEM_BYTES>>>(
        acth, rw2h, (long)DDIM * FDIM, h, DDIM, FDIM);
    combine_kernel<<<TT, 256>>>(out);
}